// round 1
// baseline (speedup 1.0000x reference)
#include <cuda_runtime.h>

#define G 8
#define NB 8192
#define THREADS 256

// Wk transposed: [h][c] = Wk[c][h], 256x512 floats
__device__ float g_WkT[256 * 512];

__global__ void wkT_kernel(const float* __restrict__ Wk) {
    int idx = blockIdx.x * blockDim.x + threadIdx.x;
    if (idx < 512 * 256) {
        int c = idx >> 8;      // 0..511
        int h = idx & 255;     // 0..255
        g_WkT[h * 512 + c] = Wk[idx];
    }
}

// Dynamic smem layout (bytes):
//   bufA : [512][G] floats  (x concat, later wn)   16384
//   kq   : [G][512] floats                          16384
//   ee   : [256][G] floats                           8192
//   q    : [256][G] floats                           8192
//   sc   : [64] floats                                256
//   qbk  : [G] floats                                  32
#define SMEM_BYTES (16384 + 16384 + 8192 + 8192 + 256 + 32 + 64)

__global__ __launch_bounds__(256, 4)
void superedge_kernel(
    const float* __restrict__ mnode0, const float* __restrict__ mnode1,
    const float* __restrict__ dnode0, const float* __restrict__ dnode1,
    const float* __restrict__ mrel0,  const float* __restrict__ drel0,
    const float* __restrict__ W_edge, const float* __restrict__ b_edge,
    const float* __restrict__ Wq,     const float* __restrict__ bq,
    const float* __restrict__ bk,
    const float* __restrict__ Wv,     const float* __restrict__ bv,
    float* __restrict__ out)
{
    extern __shared__ float smem[];
    float* bufA = smem;                 // [512][G]  x, later wn
    float* kq_s = bufA + 512 * G;       // [G][512]
    float* ee_s = kq_s + G * 512;       // [256][G]
    float* q_s  = ee_s + 256 * G;       // [256][G]
    float* sc_s = q_s + 256 * G;        // [64]
    float* qbk_s = sc_s + 64;           // [G]

    const int tid = threadIdx.x;
    const int b0 = blockIdx.x * G;

    // ---------------- Phase 1: load x = [mnode0 | dnode0] into bufA[c][g]
    #pragma unroll
    for (int g = 0; g < G; g++) {
        int b = b0 + g;
        bufA[tid * G + g]         = mnode0[(size_t)b * 256 + tid];
        bufA[(tid + 256) * G + g] = dnode0[(size_t)b * 256 + tid];
    }
    __syncthreads();

    float acc[G];

    // ---------------- Phase 2: edge_emb[h] = relu(x @ W_edge + b_edge), h = tid
    {
        float bias = b_edge[tid];
        #pragma unroll
        for (int g = 0; g < G; g++) acc[g] = bias;
        const float* Wcol = W_edge + tid;
        #pragma unroll 4
        for (int c = 0; c < 512; c++) {
            float w = Wcol[c << 8];
            float4 xa = *(const float4*)&bufA[c * G + 0];
            float4 xb = *(const float4*)&bufA[c * G + 4];
            acc[0] += xa.x * w; acc[1] += xa.y * w;
            acc[2] += xa.z * w; acc[3] += xa.w * w;
            acc[4] += xb.x * w; acc[5] += xb.y * w;
            acc[6] += xb.z * w; acc[7] += xb.w * w;
        }
        #pragma unroll
        for (int g = 0; g < G; g++) {
            float v = fmaxf(acc[g], 0.0f);
            ee_s[tid * G + g] = v;
            out[(size_t)(b0 + g) * 512 + tid] = v;   // first half of output
        }
    }
    __syncthreads();

    // ---------------- Phase 3: q[h] = edge_emb @ Wq + bq, h = tid
    {
        float bias = bq[tid];
        #pragma unroll
        for (int g = 0; g < G; g++) acc[g] = bias;
        const float* Wcol = Wq + tid;
        #pragma unroll 4
        for (int c = 0; c < 256; c++) {
            float w = Wcol[c << 8];
            float4 xa = *(const float4*)&ee_s[c * G + 0];
            float4 xb = *(const float4*)&ee_s[c * G + 4];
            acc[0] += xa.x * w; acc[1] += xa.y * w;
            acc[2] += xa.z * w; acc[3] += xa.w * w;
            acc[4] += xb.x * w; acc[5] += xb.y * w;
            acc[6] += xb.z * w; acc[7] += xb.w * w;
        }
        #pragma unroll
        for (int g = 0; g < G; g++) q_s[tid * G + g] = acc[g];
    }
    __syncthreads();

    // ---------------- qbk[g] = q_g . bk   (warp w handles g = w)
    {
        int w = tid >> 5, lane = tid & 31;
        float p = 0.0f;
        for (int h = lane; h < 256; h += 32) p += q_s[h * G + w] * bk[h];
        #pragma unroll
        for (int o = 16; o; o >>= 1) p += __shfl_xor_sync(0xffffffffu, p, o);
        if (lane == 0) qbk_s[w] = p;
    }
    // (no barrier needed yet: qbk_s consumed after the phase-4 barrier)

    // ---------------- Phase 4: kq[c] = sum_h WkT[h][c] * q[h]
    #pragma unroll
    for (int c2 = 0; c2 < 2; c2++) {
        int c = (c2 << 8) + tid;
        #pragma unroll
        for (int g = 0; g < G; g++) acc[g] = 0.0f;
        const float* Wcol = g_WkT + c;
        #pragma unroll 4
        for (int h = 0; h < 256; h++) {
            float w = Wcol[h << 9];
            float4 qa = *(const float4*)&q_s[h * G + 0];
            float4 qb = *(const float4*)&q_s[h * G + 4];
            acc[0] += qa.x * w; acc[1] += qa.y * w;
            acc[2] += qa.z * w; acc[3] += qa.w * w;
            acc[4] += qb.x * w; acc[5] += qb.y * w;
            acc[6] += qb.z * w; acc[7] += qb.w * w;
        }
        #pragma unroll
        for (int g = 0; g < G; g++) kq_s[g * 512 + c] = acc[g];
    }
    __syncthreads();

    // ---------------- Phase 5: attention per batch g
    const int w = tid >> 5, lane = tid & 31;
    for (int g = 0; g < G; g++) {
        const int b = b0 + g;
        const float* kqg = kq_s + g * 512;
        // scores: warp w handles neighbor n = ch*8 + w
        for (int ch = 0; ch < 8; ch++) {
            int n = ch * 8 + w;
            const float* rel;
            const float* node;
            if (n < 32) {
                rel  = mrel0  + ((size_t)b * 32 + n) * 256;
                node = mnode1 + ((size_t)b * 32 + n) * 256;
            } else {
                int n2 = n - 32;
                rel  = drel0  + ((size_t)b * 32 + n2) * 256;
                node = dnode1 + ((size_t)b * 32 + n2) * 256;
            }
            float p = 0.0f;
            #pragma unroll
            for (int i = 0; i < 8; i++) {
                int c = lane + (i << 5);
                p += rel[c]  * kqg[c];
                p += node[c] * kqg[c + 256];
            }
            #pragma unroll
            for (int o = 16; o; o >>= 1) p += __shfl_xor_sync(0xffffffffu, p, o);
            if (lane == 0) sc_s[n] = (p + qbk_s[g]) * 0.0625f;  // / sqrt(256)
        }
        __syncthreads();

        // softmax over the 64 scores (warp 0)
        if (tid < 32) {
            float a = sc_s[tid], bb = sc_s[tid + 32];
            float m = fmaxf(a, bb);
            #pragma unroll
            for (int o = 16; o; o >>= 1) m = fmaxf(m, __shfl_xor_sync(0xffffffffu, m, o));
            float e1 = expf(a - m), e2 = expf(bb - m);
            float s = e1 + e2;
            #pragma unroll
            for (int o = 16; o; o >>= 1) s += __shfl_xor_sync(0xffffffffu, s, o);
            float inv = 1.0f / s;
            sc_s[tid] = e1 * inv;
            sc_s[tid + 32] = e2 * inv;
        }
        __syncthreads();

        // wn[c] = sum_n attn_n * edge_nei[n][c]; thread owns float2 at c = 2*tid
        {
            int c = tid * 2;
            bool isNode = (c >= 256);
            int cc = isNode ? c - 256 : c;
            const float* am = isNode ? mnode1 : mrel0;   // n < 32
            const float* ad = isNode ? dnode1 : drel0;   // n >= 32
            const float* pm = am + (size_t)b * 32 * 256 + cc;
            const float* pd = ad + (size_t)b * 32 * 256 + cc;
            float ax = 0.0f, ay = 0.0f;
            #pragma unroll 4
            for (int n = 0; n < 32; n++) {
                float pr = sc_s[n];
                float2 vv = *(const float2*)(pm + n * 256);
                ax += pr * vv.x; ay += pr * vv.y;
            }
            #pragma unroll 4
            for (int n = 0; n < 32; n++) {
                float pr = sc_s[n + 32];
                float2 vv = *(const float2*)(pd + n * 256);
                ax += pr * vv.x; ay += pr * vv.y;
            }
            bufA[c * G + g] = ax;         // bufA reused as wn[c][g]
            bufA[(c + 1) * G + g] = ay;
        }
        __syncthreads();   // protect sc_s for next g
    }

    // ---------------- Phase 6: local_edge[h] = wn @ Wv + bv, h = tid
    {
        float bias = bv[tid];
        #pragma unroll
        for (int g = 0; g < G; g++) acc[g] = bias;
        const float* Wcol = Wv + tid;
        #pragma unroll 4
        for (int c = 0; c < 512; c++) {
            float wv = Wcol[c << 8];
            float4 xa = *(const float4*)&bufA[c * G + 0];
            float4 xb = *(const float4*)&bufA[c * G + 4];
            acc[0] += xa.x * wv; acc[1] += xa.y * wv;
            acc[2] += xa.z * wv; acc[3] += xa.w * wv;
            acc[4] += xb.x * wv; acc[5] += xb.y * wv;
            acc[6] += xb.z * wv; acc[7] += xb.w * wv;
        }
        #pragma unroll
        for (int g = 0; g < G; g++)
            out[(size_t)(b0 + g) * 512 + 256 + tid] = acc[g];  // second half
    }
}

extern "C" void kernel_launch(void* const* d_in, const int* in_sizes, int n_in,
                              void* d_out, int out_size) {
    const float* mnode0 = (const float*)d_in[0];
    const float* mnode1 = (const float*)d_in[1];
    const float* dnode0 = (const float*)d_in[2];
    const float* dnode1 = (const float*)d_in[3];
    const float* mrel0  = (const float*)d_in[4];
    const float* drel0  = (const float*)d_in[5];
    const float* W_edge = (const float*)d_in[6];
    const float* b_edge = (const float*)d_in[7];
    const float* Wq     = (const float*)d_in[8];
    const float* bq     = (const float*)d_in[9];
    const float* Wk     = (const float*)d_in[10];
    const float* bk     = (const float*)d_in[11];
    const float* Wv     = (const float*)d_in[12];
    const float* bv     = (const float*)d_in[13];
    float* out = (float*)d_out;

    cudaFuncSetAttribute(superedge_kernel,
                         cudaFuncAttributeMaxDynamicSharedMemorySize, SMEM_BYTES);

    wkT_kernel<<<512, 256>>>(Wk);
    superedge_kernel<<<NB / G, THREADS, SMEM_BYTES>>>(
        mnode0, mnode1, dnode0, dnode1, mrel0, drel0,
        W_edge, b_edge, Wq, bq, bk, Wv, bv, out);
}